// round 16
// baseline (speedup 1.0000x reference)
#include <cuda_runtime.h>
#include <math_constants.h>

// ChamferDistance: x (8,8192,3) f32, y (8,8192,3) f32 -> scalar f32.
// FMA-pipe bound brute force with packed fma.rn.f32x2 (FFMA2).
//   d^2(q,r) = qq + (rr - 2*dot(q,r)); queries pre-scaled by -2.
//   min(sqrt(v+EPS)) == sqrt(min(v)+EPS) -> one sqrt per point at the end.
// R16: R14 champion pass + atomic-key global mins. For v>=0,
// key = ~bits(v) is monotone DECREASING -> atomicMax(unsigned) == float min,
// and the zero .bss state (key 0) acts as +inf: NO init kernel. Reduce resets
// keys to 0 after reading (graph-replay deterministic). Kills the 16MB
// g_minpart round-trip that made the reduce cost 11.6us (now ~512KB).

#define BATCH   8
#define NPTS    8192
#define RSPLIT  32
#define TPB     128
#define U       8                              // queries per thread
#define QPB     (TPB * U)                      // 1024 queries per block
#define QBLK    (NPTS / QPB)                   // 8
#define RCHUNK  (NPTS / RSPLIT)                // 256 refs per block (one stage)
#define EPS_F   1e-10f

__device__ unsigned g_min[2][BATCH * NPTS];    // .bss zeros == key(+inf)
__device__ float    g_partial[64];
__device__ int      g_ticket;                  // self-resetting completion counter

__device__ __forceinline__ unsigned long long f2_fma(unsigned long long a, unsigned long long b, unsigned long long c) {
    unsigned long long d;
    asm("fma.rn.f32x2 %0, %1, %2, %3;" : "=l"(d) : "l"(a), "l"(b), "l"(c));
    return d;
}
__device__ __forceinline__ unsigned long long f2_pack(float a, float b) {
    unsigned long long r;
    asm("mov.b64 %0, {%1, %2};" : "=l"(r) : "f"(a), "f"(b));
    return r;
}
__device__ __forceinline__ void f2_unpack(unsigned long long v, float& lo, float& hi) {
    asm("mov.b64 {%0, %1}, %2;" : "=f"(lo), "=f"(hi) : "l"(v));
}

// grid: (QBLK=8, RSPLIT=32, 16) where z = dir*8 + b
__global__ __launch_bounds__(TPB, 7)
void chamfer_pass_kernel(const float* __restrict__ x, const float* __restrict__ y) {
    const int dir = blockIdx.z >> 3;
    const int b   = blockIdx.z & 7;
    const float* __restrict__ Q = dir ? y : x;   // query side
    const float* __restrict__ R = dir ? x : y;   // reference side

    const int t = threadIdx.x;

    // Pair-interleaved chunk (256 refs = 128 pairs), staged ONCE per block:
    //   sm[8j+0..1]=x pair, [8j+2..3]=y pair, [8j+4..5]=z pair, [8j+6..7]=rr pair
    __shared__ float sm[RCHUNK * 4];

    // Stage: each thread loads 2 ref points (t and t+128).
    {
        const float* rp = R + ((size_t)b * NPTS + blockIdx.y * RCHUNK + t) * 3;
#pragma unroll
        for (int h = 0; h < 2; h++) {
            float rx = rp[0], ry = rp[1], rz = rp[2];
            const int idx = t + h * TPB;
            const int jj  = (idx >> 1) * 8 + (idx & 1);
            sm[jj + 0] = rx;
            sm[jj + 2] = ry;
            sm[jj + 4] = rz;
            sm[jj + 6] = rx * rx + ry * ry + rz * rz;
            rp += TPB * 3;
        }
    }

    float minv[U];
    unsigned long long qx2[U], qy2[U], qz2[U];   // query coords pre-scaled by -2, splatted
    {
        const float* qp = Q + ((size_t)b * NPTS + blockIdx.x * QPB + t) * 3;
#pragma unroll
        for (int u = 0; u < U; u++) {
            float a = qp[0] * -2.0f, c = qp[1] * -2.0f, e = qp[2] * -2.0f;
            qx2[u] = f2_pack(a, a);
            qy2[u] = f2_pack(c, c);
            qz2[u] = f2_pack(e, e);
            minv[u] = CUDART_INF_F;
            qp += TPB * 3;
        }
    }
    __syncthreads();   // the ONLY barrier: staged chunk visible

#pragma unroll 4
    for (int j = 0; j < RCHUNK / 2; j++) {
        // Two LDS.128 -> four pre-packed f32x2 operands (broadcast, conflict-free),
        // each pair reused by 8 queries.
        ulonglong2 A  = *reinterpret_cast<const ulonglong2*>(&sm[8 * j]);      // {x-pair, y-pair}
        ulonglong2 Bv = *reinterpret_cast<const ulonglong2*>(&sm[8 * j + 4]);  // {z-pair, rr-pair}
#pragma unroll
        for (int u = 0; u < U; u++) {
            unsigned long long acc = f2_fma(qx2[u], A.x, Bv.y);  // rr - 2 qx rx
            acc = f2_fma(qy2[u], A.y, acc);
            acc = f2_fma(qz2[u], Bv.x, acc);                     // rr - 2 dot (packed x2)
            float lo, hi;
            f2_unpack(acc, lo, hi);
            minv[u] = fminf(minv[u], fminf(lo, hi));
        }
    }

    // Epilogue: add qq (L1-hot reload) and fold into global key-mins.
    {
        const int qidx0 = b * NPTS + blockIdx.x * QPB + t;
        const float* qp = Q + (size_t)qidx0 * 3;
#pragma unroll
        for (int u = 0; u < U; u++) {
            float qq = qp[0] * qp[0] + qp[1] * qp[1] + qp[2] * qp[2];
            float v  = fmaxf(minv[u] + qq, 0.0f);
            atomicMax(&g_min[dir][qidx0 + u * TPB], ~__float_as_uint(v));
            qp += TPB * 3;
        }
    }
}

// 64 blocks: dir(2) x b(8) x quarter(4); each covers 2048 queries (8KB keys).
// Decodes keys, sums sqrt, resets keys to 0 for the next replay; the last
// block (ticket) performs the final combine and writes the scalar.
__global__ __launch_bounds__(256)
void chamfer_reduce_kernel(float* __restrict__ out) {
    const int dir     = blockIdx.x >> 5;
    const int b       = (blockIdx.x >> 2) & 7;
    const int quarter = blockIdx.x & 3;
    const int t       = threadIdx.x;
    unsigned* __restrict__ arr = &g_min[dir][b * NPTS + quarter * 2048];

    float s = 0.0f;
#pragma unroll
    for (int k = 0; k < 8; k++) {
        const int idx = k * 256 + t;
        float v = __uint_as_float(~arr[idx]);
        s += sqrtf(v + EPS_F);
        arr[idx] = 0u;                          // reset: key 0 == +inf
    }

    __shared__ float red[256];
    red[t] = s;
    __syncthreads();
    for (int o = 128; o > 0; o >>= 1) {
        if (t < o) red[t] += red[t + o];
        __syncthreads();
    }

    __shared__ bool amLast;
    if (t == 0) {
        g_partial[blockIdx.x] = red[0];
        __threadfence();
        amLast = (atomicAdd(&g_ticket, 1) == 63);
    }
    __syncthreads();

    if (amLast) {
        // 64 partials: lane t<16 owns (dir,b)=t, sums its 4 quarters.
        if (t < 16) {
            float ps = 0.0f;
#pragma unroll
            for (int c = 0; c < 4; c++) ps += g_partial[t * 4 + c];
            red[t] = ps;
        }
        __syncthreads();
        if (t == 0) {
            float s2 = 0.0f;
#pragma unroll
            for (int bb = 0; bb < BATCH; bb++)
                s2 += fmaxf(red[bb], red[8 + bb]) * (1.0f / (float)NPTS);
            *out = s2;
            g_ticket = 0;          // reset for next graph replay (deterministic)
        }
    }
}

extern "C" void kernel_launch(void* const* d_in, const int* in_sizes, int n_in,
                              void* d_out, int out_size) {
    const float* x = (const float*)d_in[0];
    const float* y = (const float*)d_in[1];
    float* out = (float*)d_out;

    dim3 grid(QBLK, RSPLIT, 16);                 // 8 x 32 x 16 = 4096 blocks
    chamfer_pass_kernel<<<grid, TPB>>>(x, y);
    chamfer_reduce_kernel<<<64, 256>>>(out);
}

// round 17
// speedup vs baseline: 1.5780x; 1.5780x over previous
#include <cuda_runtime.h>
#include <math_constants.h>

// ChamferDistance: x (8,8192,3) f32, y (8,8192,3) f32 -> scalar f32.
// FMA-pipe bound brute force with packed fma.rn.f32x2 (FFMA2).
//   d^2(q,r) = qq + (rr - 2*dot(q,r)); queries pre-scaled by -2; qq added in reduce.
//   min(sqrt(v+EPS)) == sqrt(min(v)+EPS) -> one sqrt per point at the end.
// R17: pass kernel IDENTICAL to R14 champion (118us; no atomics -- R16 proved
// pass-epilogue global atomics cost +70us). Reduce re-gridded 128->512 blocks:
// R14's reduce was parallelism-starved (occ 12.5%, issue 4.3%, DRAM 20%);
// 512x256 with 32 independent coalesced loads/thread turns the 16MB sweep
// BW-bound (~3us). Still 2 kernels total via ticket final combine.

#define BATCH   8
#define NPTS    8192
#define RSPLIT  32
#define TPB     128
#define U       8                              // queries per thread
#define QPB     (TPB * U)                      // 1024 queries per block
#define QBLK    (NPTS / QPB)                   // 8
#define RCHUNK  (NPTS / RSPLIT)                // 256 refs per block (one stage)
#define EPS_F   1e-10f
#define RBLK    512                            // reduce grid

__device__ float g_minpart[2][RSPLIT][BATCH * NPTS];
__device__ float g_partial[RBLK];
__device__ int   g_ticket;                     // self-resetting completion counter

__device__ __forceinline__ unsigned long long f2_fma(unsigned long long a, unsigned long long b, unsigned long long c) {
    unsigned long long d;
    asm("fma.rn.f32x2 %0, %1, %2, %3;" : "=l"(d) : "l"(a), "l"(b), "l"(c));
    return d;
}
__device__ __forceinline__ unsigned long long f2_pack(float a, float b) {
    unsigned long long r;
    asm("mov.b64 %0, {%1, %2};" : "=l"(r) : "f"(a), "f"(b));
    return r;
}
__device__ __forceinline__ void f2_unpack(unsigned long long v, float& lo, float& hi) {
    asm("mov.b64 {%0, %1}, %2;" : "=f"(lo), "=f"(hi) : "l"(v));
}

// grid: (QBLK=8, RSPLIT=32, 16) where z = dir*8 + b
__global__ __launch_bounds__(TPB, 7)
void chamfer_pass_kernel(const float* __restrict__ x, const float* __restrict__ y) {
    const int dir = blockIdx.z >> 3;
    const int b   = blockIdx.z & 7;
    const float* __restrict__ Q = dir ? y : x;   // query side
    const float* __restrict__ R = dir ? x : y;   // reference side

    const int t = threadIdx.x;

    // Pair-interleaved chunk (256 refs = 128 pairs), staged ONCE per block:
    //   sm[8j+0..1]=x pair, [8j+2..3]=y pair, [8j+4..5]=z pair, [8j+6..7]=rr pair
    __shared__ float sm[RCHUNK * 4];

    // Stage: each thread loads 2 ref points (t and t+128).
    {
        const float* rp = R + ((size_t)b * NPTS + blockIdx.y * RCHUNK + t) * 3;
#pragma unroll
        for (int h = 0; h < 2; h++) {
            float rx = rp[0], ry = rp[1], rz = rp[2];
            const int idx = t + h * TPB;
            const int jj  = (idx >> 1) * 8 + (idx & 1);
            sm[jj + 0] = rx;
            sm[jj + 2] = ry;
            sm[jj + 4] = rz;
            sm[jj + 6] = rx * rx + ry * ry + rz * rz;
            rp += TPB * 3;
        }
    }

    float minv[U];
    unsigned long long qx2[U], qy2[U], qz2[U];   // query coords pre-scaled by -2, splatted
    {
        const float* qp = Q + ((size_t)b * NPTS + blockIdx.x * QPB + t) * 3;
#pragma unroll
        for (int u = 0; u < U; u++) {
            float a = qp[0] * -2.0f, c = qp[1] * -2.0f, e = qp[2] * -2.0f;
            qx2[u] = f2_pack(a, a);
            qy2[u] = f2_pack(c, c);
            qz2[u] = f2_pack(e, e);
            minv[u] = CUDART_INF_F;
            qp += TPB * 3;
        }
    }
    __syncthreads();   // the ONLY barrier: staged chunk visible

#pragma unroll 4
    for (int j = 0; j < RCHUNK / 2; j++) {
        // Two LDS.128 -> four pre-packed f32x2 operands (broadcast, conflict-free),
        // each pair reused by 8 queries.
        ulonglong2 A  = *reinterpret_cast<const ulonglong2*>(&sm[8 * j]);      // {x-pair, y-pair}
        ulonglong2 Bv = *reinterpret_cast<const ulonglong2*>(&sm[8 * j + 4]);  // {z-pair, rr-pair}
#pragma unroll
        for (int u = 0; u < U; u++) {
            unsigned long long acc = f2_fma(qx2[u], A.x, Bv.y);  // rr - 2 qx rx
            acc = f2_fma(qy2[u], A.y, acc);
            acc = f2_fma(qz2[u], Bv.x, acc);                     // rr - 2 dot (packed x2)
            float lo, hi;
            f2_unpack(acc, lo, hi);
            minv[u] = fminf(minv[u], fminf(lo, hi));
        }
    }

    float* outp = &g_minpart[dir][blockIdx.y][b * NPTS + blockIdx.x * QPB + t];
#pragma unroll
    for (int u = 0; u < U; u++) {
        outp[u * TPB] = minv[u];
    }
}

// 512 blocks x 256 threads: one query per thread (qglobal = blk*256 + t),
// 32 independent coalesced loads across the RSPLIT partials (MLP=32), add qq,
// sqrt, block-sum. Each block lies within one (dir,b) segment (8192 = 32 blks).
// Last block (ticket) combines the 512 partials and writes the scalar.
__global__ __launch_bounds__(256)
void chamfer_reduce_kernel(const float* __restrict__ x, const float* __restrict__ y,
                           float* __restrict__ out) {
    const int t       = threadIdx.x;
    const int qglobal = blockIdx.x * 256 + t;          // 0..131071
    const int dir     = qglobal >> 16;                 // 0..1
    const int q       = qglobal & 65535;               // index into [BATCH*NPTS]
    const float* __restrict__ Qside = dir ? y : x;

    float v = g_minpart[dir][0][q];
#pragma unroll
    for (int r = 1; r < RSPLIT; r++) v = fminf(v, g_minpart[dir][r][q]);

    const float* p = Qside + (size_t)q * 3;
    float qq = p[0] * p[0] + p[1] * p[1] + p[2] * p[2];
    float s = sqrtf(v + qq + EPS_F);

    __shared__ float red[256];
    red[t] = s;
    __syncthreads();
    for (int o = 128; o > 0; o >>= 1) {
        if (t < o) red[t] += red[t + o];
        __syncthreads();
    }

    __shared__ bool amLast;
    if (t == 0) {
        g_partial[blockIdx.x] = red[0];
        __threadfence();
        amLast = (atomicAdd(&g_ticket, 1) == RBLK - 1);
    }
    __syncthreads();

    if (amLast) {
        // 512 partials; (dir,b) segment db = blockIdx/32. Lane t<16 sums its 32.
        if (t < 16) {
            float ps = 0.0f;
#pragma unroll
            for (int c = 0; c < 32; c++) ps += g_partial[t * 32 + c];
            red[t] = ps;
        }
        __syncthreads();
        if (t == 0) {
            float s2 = 0.0f;
#pragma unroll
            for (int bb = 0; bb < BATCH; bb++)
                s2 += fmaxf(red[bb], red[8 + bb]) * (1.0f / (float)NPTS);
            *out = s2;
            g_ticket = 0;          // reset for next graph replay (deterministic)
        }
    }
}

extern "C" void kernel_launch(void* const* d_in, const int* in_sizes, int n_in,
                              void* d_out, int out_size) {
    const float* x = (const float*)d_in[0];
    const float* y = (const float*)d_in[1];
    float* out = (float*)d_out;

    dim3 grid(QBLK, RSPLIT, 16);                 // 8 x 32 x 16 = 4096 blocks
    chamfer_pass_kernel<<<grid, TPB>>>(x, y);
    chamfer_reduce_kernel<<<RBLK, 256>>>(x, y, out);
}